// round 3
// baseline (speedup 1.0000x reference)
#include <cuda_runtime.h>
#include <math.h>

#define Cc 64
#define Hh 192
#define Ww 192
#define HW (Hh*Ww)            // 36864
#define Bb 4
#define NPIX (Bb*HW)          // 147456
#define NTOT (Bb*Cc*HW)       // 9437184
#define NSPLIT 36
#define HEADS 2

// ---------------- scratch (static device memory; no allocs) ----------------
__device__ float g_bufA[NTOT];
__device__ float g_bufB[NTOT];
__device__ float g_bufC[NTOT];   // x1 (kept)
__device__ float g_bufD[NTOT];
__device__ float g_bufE[NTOT];   // out1 (kept)
__device__ float g_bufF[NTOT];   // out2
__device__ float g_bufG[NTOT];   // out3
__device__ float g_invQ[Bb*Cc];
__device__ float g_invK[Bb*Cc];
__device__ float g_attn[Bb*HEADS*32*32];
__device__ float g_M[Bb*Cc*Cc];

__device__ __forceinline__ float gelu_erf(float v){
    return 0.5f*v*(1.f+erff(v*0.70710678118654752f));
}

// ---------------- generic 1x1 conv, no bias: y[b,o,n] = sum_c w[o,c] x[b,c,n]
__global__ void conv1x1_nb(const float* __restrict__ x, const float* __restrict__ w,
                           float* __restrict__ y){
    __shared__ float ws[64*64];  // transposed: ws[c*64+o]
    for (int idx = threadIdx.x; idx < 4096; idx += blockDim.x){
        int o = idx >> 6, c = idx & 63;
        ws[c*64 + o] = w[idx];
    }
    __syncthreads();
    int p = blockIdx.x * blockDim.x + threadIdx.x;
    int b = p / HW; int n = p - b*HW;
    const float* xb = x + (size_t)b*Cc*HW + n;
    float acc[64];
    #pragma unroll
    for (int o=0;o<64;o++) acc[o]=0.f;
    #pragma unroll 4
    for (int c=0;c<64;c++){
        float xv = __ldg(xb + (size_t)c*HW);
        const float4* wr = (const float4*)(ws + c*64);
        #pragma unroll
        for (int o4=0;o4<16;o4++){
            float4 wv = wr[o4];
            acc[o4*4+0] += wv.x*xv; acc[o4*4+1] += wv.y*xv;
            acc[o4*4+2] += wv.z*xv; acc[o4*4+3] += wv.w*xv;
        }
    }
    float* yb = y + (size_t)b*Cc*HW + n;
    #pragma unroll
    for (int o=0;o<64;o++) yb[(size_t)o*HW] = acc[o];
}

// ---------------- 1x1 conv with PER-BATCH weights (channel-attn out1 = M_b @ V)
__global__ void conv1x1_batch(const float* __restrict__ x, const float* __restrict__ wAll,
                              float* __restrict__ y){
    __shared__ float ws[64*64];
    int b0 = (blockIdx.x * blockDim.x) / HW;         // whole block shares batch
    const float* w = wAll + (size_t)b0*4096;
    for (int idx = threadIdx.x; idx < 4096; idx += blockDim.x){
        int o = idx >> 6, c = idx & 63;
        ws[c*64 + o] = w[idx];
    }
    __syncthreads();
    int p = blockIdx.x * blockDim.x + threadIdx.x;
    int b = p / HW; int n = p - b*HW;
    const float* xb = x + (size_t)b*Cc*HW + n;
    float acc[64];
    #pragma unroll
    for (int o=0;o<64;o++) acc[o]=0.f;
    #pragma unroll 4
    for (int c=0;c<64;c++){
        float xv = __ldg(xb + (size_t)c*HW);
        const float4* wr = (const float4*)(ws + c*64);
        #pragma unroll
        for (int o4=0;o4<16;o4++){
            float4 wv = wr[o4];
            acc[o4*4+0] += wv.x*xv; acc[o4*4+1] += wv.y*xv;
            acc[o4*4+2] += wv.z*xv; acc[o4*4+3] += wv.w*xv;
        }
    }
    float* yb = y + (size_t)b*Cc*HW + n;
    #pragma unroll
    for (int o=0;o<64;o++) yb[(size_t)o*HW] = acc[o];
}

// ---------------- depthwise 3x3 + bias
__global__ void dwconv(const float* __restrict__ x, const float* __restrict__ w,
                       const float* __restrict__ bias, float* __restrict__ y){
    int idx = blockIdx.x*256 + threadIdx.x;
    if (idx >= NTOT) return;
    int n  = idx % HW;
    int bc = idx / HW;
    int c  = bc & 63;
    int h = n / Ww, wc = n - h*Ww;
    const float* wp = w + c*9;
    float acc = bias[c];
    #pragma unroll
    for (int dy=-1;dy<=1;dy++){
        int hh = h + dy;
        if (hh < 0 || hh >= Hh) continue;
        #pragma unroll
        for (int dx=-1;dx<=1;dx++){
            int ww2 = wc + dx;
            if (ww2 < 0 || ww2 >= Ww) continue;
            acc += wp[(dy+1)*3 + (dx+1)] * x[idx + dy*Ww + dx];
        }
    }
    y[idx] = acc;
}

// ---------------- x1 = conv2(gelu(t2)) + b2 + conv0(x) + b0
__global__ void x1_fuse(const float* __restrict__ t2, const float* __restrict__ x,
                        const float* __restrict__ w2, const float* __restrict__ b2,
                        const float* __restrict__ w0, const float* __restrict__ b0,
                        float* __restrict__ y){
    __shared__ float ws2[4096], ws0[4096];
    for (int idx = threadIdx.x; idx < 4096; idx += blockDim.x){
        int o = idx >> 6, c = idx & 63;
        ws2[c*64+o] = w2[idx];
        ws0[c*64+o] = w0[idx];
    }
    __syncthreads();
    int p = blockIdx.x * blockDim.x + threadIdx.x;
    int b = p / HW; int n = p - b*HW;
    const float* tb = t2 + (size_t)b*Cc*HW + n;
    const float* xb = x  + (size_t)b*Cc*HW + n;
    float acc[64];
    #pragma unroll
    for (int o=0;o<64;o++) acc[o] = b2[o] + b0[o];
    #pragma unroll 2
    for (int c=0;c<64;c++){
        float gv = gelu_erf(__ldg(tb + (size_t)c*HW));
        float xv = __ldg(xb + (size_t)c*HW);
        const float4* w2r = (const float4*)(ws2 + c*64);
        const float4* w0r = (const float4*)(ws0 + c*64);
        #pragma unroll
        for (int o4=0;o4<16;o4++){
            float4 a = w2r[o4], bwv = w0r[o4];
            acc[o4*4+0] += a.x*gv + bwv.x*xv;
            acc[o4*4+1] += a.y*gv + bwv.y*xv;
            acc[o4*4+2] += a.z*gv + bwv.z*xv;
            acc[o4*4+3] += a.w*gv + bwv.w*xv;
        }
    }
    float* yb = y + (size_t)b*Cc*HW + n;
    #pragma unroll
    for (int o=0;o<64;o++) yb[(size_t)o*HW] = acc[o];
}

// ---------------- per-(b,channel) 1/max(||.||,1e-12) over HW, for Q and K
__global__ void norm_kernel(const float* __restrict__ Q, const float* __restrict__ K,
                            float* __restrict__ invQ, float* __restrict__ invK){
    const float* src = blockIdx.y ? K : Q;
    size_t base = (size_t)blockIdx.x * HW;
    float s = 0.f;
    for (int i = threadIdx.x; i < HW; i += 256){
        float v = src[base + i]; s += v*v;
    }
    #pragma unroll
    for (int o=16;o;o>>=1) s += __shfl_xor_sync(0xffffffffu, s, o);
    __shared__ float red[8];
    int warp = threadIdx.x >> 5, lane = threadIdx.x & 31;
    if (lane == 0) red[warp] = s;
    __syncthreads();
    if (threadIdx.x == 0){
        float t = 0.f;
        #pragma unroll
        for (int i=0;i<8;i++) t += red[i];
        float inv = 1.f / fmaxf(sqrtf(t), 1e-12f);
        (blockIdx.y ? invK : invQ)[blockIdx.x] = inv;
    }
}

__global__ void zero_attn(float* __restrict__ a){
    int i = blockIdx.x*256 + threadIdx.x;
    if (i < Bb*HEADS*32*32) a[i] = 0.f;
}

// ---------------- attn_raw[bg,c,d] += sum_n Q[c,n]K[d,n] over an n-chunk
__global__ void attn_dot(const float* __restrict__ Q, const float* __restrict__ K,
                         float* __restrict__ attn){
    __shared__ float Qs[32][33], Ks[32][33];
    int bg = blockIdx.x;               // 0..7 = b*2+g
    int b = bg >> 1, g = bg & 1;
    size_t base = ((size_t)b*Cc + g*32) * HW;
    int chunk = HW / NSPLIT;           // 1024
    int nstart = blockIdx.y * chunk;
    int c = threadIdx.y, d = threadIdx.x;
    float acc = 0.f;
    for (int n0 = nstart; n0 < nstart + chunk; n0 += 32){
        Qs[threadIdx.y][threadIdx.x] = Q[base + (size_t)threadIdx.y*HW + n0 + threadIdx.x];
        Ks[threadIdx.y][threadIdx.x] = K[base + (size_t)threadIdx.y*HW + n0 + threadIdx.x];
        __syncthreads();
        #pragma unroll
        for (int nn=0;nn<32;nn++) acc += Qs[c][nn]*Ks[d][nn];
        __syncthreads();
    }
    atomicAdd(&attn[(bg*32 + c)*32 + d], acc);
}

// ---------------- softmax on attn, then M_b[o, g*32+d] = sum_c proj[o,g*32+c]*attn[c,d]
__global__ void softmax_M(const float* __restrict__ proj, const float* __restrict__ temp,
                          const float* __restrict__ attn,
                          const float* __restrict__ invQ, const float* __restrict__ invK,
                          float* __restrict__ M){
    __shared__ float at[32][33];
    int bg = blockIdx.x, b = bg >> 1, g = bg & 1;
    int t = threadIdx.x;
    int w = t >> 5, lane = t & 31;      // warp w handles attn row c=w
    float v = attn[(bg*32 + w)*32 + lane]
            * invQ[b*Cc + g*32 + w] * invK[b*Cc + g*32 + lane] * temp[g];
    float m = v;
    #pragma unroll
    for (int o=16;o;o>>=1) m = fmaxf(m, __shfl_xor_sync(0xffffffffu, m, o));
    v = __expf(v - m);
    float s = v;
    #pragma unroll
    for (int o=16;o;o>>=1) s += __shfl_xor_sync(0xffffffffu, s, o);
    at[w][lane] = v / s;
    __syncthreads();
    // 1024 threads -> 2048 outputs: o0 = t>>5 plus o0+32; d = lane
    int o0 = t >> 5;
    float m0 = 0.f, m1 = 0.f;
    #pragma unroll 4
    for (int c2=0;c2<32;c2++){
        float a = at[c2][lane];
        m0 += __ldg(&proj[o0*Cc       + g*32 + c2]) * a;
        m1 += __ldg(&proj[(o0+32)*Cc  + g*32 + c2]) * a;
    }
    M[((size_t)b*Cc + o0     )*Cc + g*32 + lane] = m0;
    M[((size_t)b*Cc + o0 + 32)*Cc + g*32 + lane] = m1;
}

// ---------------- row/col attention (one line per block)
// element (c,pos) of a line: addr = base + c*HW + pos*posStride
// row: lineStride=W (line=h), posStride=1 ; col: lineStride=1 (line=w), posStride=W
__global__ void line_attn(const float* __restrict__ Q, const float* __restrict__ K,
                          const float* __restrict__ V, const float* __restrict__ x1,
                          float* __restrict__ out, const float* __restrict__ gamma_p,
                          int lineStride, int posStride){
    extern __shared__ float sm[];
    float* Qs = sm;                 // [64][200]
    float* Ks = Qs + 64*200;
    float* Vs = Ks + 64*200;
    float* st = Vs + 64*200;        // [32][200]
    int b = blockIdx.x / 192;
    int line = blockIdx.x - b*192;
    size_t base = (size_t)b*Cc*HW + (size_t)line*lineStride;
    int t = threadIdx.x;
    for (int idx = t; idx < 64*192; idx += 256){
        int c = idx / 192, p = idx - c*192;
        size_t ga = base + (size_t)c*HW + (size_t)p*posStride;
        Qs[c*200+p] = Q[ga];
        Ks[c*200+p] = K[ga];
        Vs[c*200+p] = V[ga];
    }
    __syncthreads();
    float gamma = *gamma_p;

    for (int i0 = 0; i0 < 192; i0 += 32){
        // --- s tile: 32 rows x 192 cols ---
        int ihalf = t >> 4, jg = t & 15, j0 = jg * 12;
        float acc0[12], acc1[12];
        #pragma unroll
        for (int jj=0;jj<12;jj++){ acc0[jj]=0.f; acc1[jj]=0.f; }
        #pragma unroll 4
        for (int c=0;c<64;c++){
            float q0 = Qs[c*200 + i0 + ihalf];
            float q1 = Qs[c*200 + i0 + ihalf + 16];
            const float4* kr = (const float4*)(&Ks[c*200 + j0]);
            float4 k0 = kr[0], k1 = kr[1], k2 = kr[2];
            acc0[0]+=q0*k0.x; acc0[1]+=q0*k0.y; acc0[2]+=q0*k0.z; acc0[3]+=q0*k0.w;
            acc0[4]+=q0*k1.x; acc0[5]+=q0*k1.y; acc0[6]+=q0*k1.z; acc0[7]+=q0*k1.w;
            acc0[8]+=q0*k2.x; acc0[9]+=q0*k2.y; acc0[10]+=q0*k2.z; acc0[11]+=q0*k2.w;
            acc1[0]+=q1*k0.x; acc1[1]+=q1*k0.y; acc1[2]+=q1*k0.z; acc1[3]+=q1*k0.w;
            acc1[4]+=q1*k1.x; acc1[5]+=q1*k1.y; acc1[6]+=q1*k1.z; acc1[7]+=q1*k1.w;
            acc1[8]+=q1*k2.x; acc1[9]+=q1*k2.y; acc1[10]+=q1*k2.z; acc1[11]+=q1*k2.w;
        }
        #pragma unroll
        for (int jj=0;jj<12;jj++){
            st[ihalf*200 + j0 + jj]      = acc0[jj];
            st[(ihalf+16)*200 + j0 + jj] = acc1[jj];
        }
        __syncthreads();
        // --- softmax over j per row: warp w handles rows w, w+8, w+16, w+24 ---
        int warp = t >> 5, lane = t & 31;
        #pragma unroll
        for (int rr=0;rr<4;rr++){
            int r = warp + rr*8;
            float vals[6]; float mx = -3.4e38f;
            #pragma unroll
            for (int e=0;e<6;e++){ vals[e] = st[r*200 + lane + e*32]; mx = fmaxf(mx, vals[e]); }
            #pragma unroll
            for (int o=16;o;o>>=1) mx = fmaxf(mx, __shfl_xor_sync(0xffffffffu, mx, o));
            float sme = 0.f;
            #pragma unroll
            for (int e=0;e<6;e++){ vals[e] = __expf(vals[e]-mx); sme += vals[e]; }
            #pragma unroll
            for (int o=16;o;o>>=1) sme += __shfl_xor_sync(0xffffffffu, sme, o);
            float inv = 1.f/sme;
            #pragma unroll
            for (int e=0;e<6;e++) st[r*200 + lane + e*32] = vals[e]*inv;
        }
        __syncthreads();
        // --- out tile: each thread 2 channels x 4 i-rows ---
        int cg = t >> 3, ig = t & 7;
        int c0 = cg*2;
        float oa[8];
        #pragma unroll
        for (int z=0;z<8;z++) oa[z]=0.f;
        #pragma unroll 4
        for (int j=0;j<192;j++){
            float v0 = Vs[c0*200 + j], v1 = Vs[(c0+1)*200 + j];
            #pragma unroll
            for (int m=0;m<4;m++){
                float a = st[(ig + 8*m)*200 + j];
                oa[m]   += v0*a;
                oa[4+m] += v1*a;
            }
        }
        #pragma unroll
        for (int m=0;m<4;m++){
            int i = i0 + ig + 8*m;
            size_t ga0 = base + (size_t)c0*HW     + (size_t)i*posStride;
            size_t ga1 = base + (size_t)(c0+1)*HW + (size_t)i*posStride;
            out[ga0] = gamma*oa[m]   + x1[ga0];
            out[ga1] = gamma*oa[4+m] + x1[ga1];
        }
        __syncthreads();
    }
}

// ---------------- final: gelu( Wf [out1;out2;out3] + bf )
__global__ void final_conv(const float* __restrict__ o1, const float* __restrict__ o2,
                           const float* __restrict__ o3, const float* __restrict__ w,
                           const float* __restrict__ bias, float* __restrict__ out){
    __shared__ float ws[192*64];  // ws[c*64+o], w layout [o][192]
    for (int idx = threadIdx.x; idx < 192*64; idx += blockDim.x){
        int o = idx / 192, c = idx - o*192;
        ws[c*64 + o] = w[idx];
    }
    __syncthreads();
    int p = blockIdx.x * blockDim.x + threadIdx.x;
    int b = p / HW; int n = p - b*HW;
    const float* p1 = o1 + (size_t)b*Cc*HW + n;
    const float* p2 = o2 + (size_t)b*Cc*HW + n;
    const float* p3 = o3 + (size_t)b*Cc*HW + n;
    float acc[64];
    #pragma unroll
    for (int o=0;o<64;o++) acc[o] = bias[o];
    #pragma unroll 2
    for (int c=0;c<64;c++){
        float xv = __ldg(p1 + (size_t)c*HW);
        const float4* wr = (const float4*)(ws + c*64);
        #pragma unroll
        for (int o4=0;o4<16;o4++){
            float4 wv = wr[o4];
            acc[o4*4+0]+=wv.x*xv; acc[o4*4+1]+=wv.y*xv;
            acc[o4*4+2]+=wv.z*xv; acc[o4*4+3]+=wv.w*xv;
        }
    }
    #pragma unroll 2
    for (int c=0;c<64;c++){
        float xv = __ldg(p2 + (size_t)c*HW);
        const float4* wr = (const float4*)(ws + (64+c)*64);
        #pragma unroll
        for (int o4=0;o4<16;o4++){
            float4 wv = wr[o4];
            acc[o4*4+0]+=wv.x*xv; acc[o4*4+1]+=wv.y*xv;
            acc[o4*4+2]+=wv.z*xv; acc[o4*4+3]+=wv.w*xv;
        }
    }
    #pragma unroll 2
    for (int c=0;c<64;c++){
        float xv = __ldg(p3 + (size_t)c*HW);
        const float4* wr = (const float4*)(ws + (128+c)*64);
        #pragma unroll
        for (int o4=0;o4<16;o4++){
            float4 wv = wr[o4];
            acc[o4*4+0]+=wv.x*xv; acc[o4*4+1]+=wv.y*xv;
            acc[o4*4+2]+=wv.z*xv; acc[o4*4+3]+=wv.w*xv;
        }
    }
    float* yb = out + (size_t)b*Cc*HW + n;
    #pragma unroll
    for (int o=0;o<64;o++) yb[(size_t)o*HW] = gelu_erf(acc[o]);
}

// =====================================================================
extern "C" void kernel_launch(void* const* d_in, const int* in_sizes, int n_in,
                              void* d_out, int out_size){
    (void)in_sizes; (void)n_in; (void)out_size;
    const float* x        = (const float*)d_in[0];
    const float* pw_w     = (const float*)d_in[1];
    const float* dw_w     = (const float*)d_in[2];
    const float* dw_b     = (const float*)d_in[3];
    const float* conv2_w  = (const float*)d_in[4];
    const float* conv2_b  = (const float*)d_in[5];
    const float* conv0_w  = (const float*)d_in[6];
    const float* conv0_b  = (const float*)d_in[7];
    const float* att_q_w  = (const float*)d_in[8];
    const float* att_k_w  = (const float*)d_in[9];
    const float* att_v_w  = (const float*)d_in[10];
    const float* att_p_w  = (const float*)d_in[11];
    const float* temp     = (const float*)d_in[12];
    const float* row_q_w  = (const float*)d_in[13];
    const float* row_k_w  = (const float*)d_in[14];
    const float* row_v_w  = (const float*)d_in[15];
    const float* row_g    = (const float*)d_in[16];
    const float* col_q_w  = (const float*)d_in[17];
    const float* col_k_w  = (const float*)d_in[18];
    const float* col_v_w  = (const float*)d_in[19];
    const float* col_g    = (const float*)d_in[20];
    const float* conv_w   = (const float*)d_in[21];
    const float* conv_b   = (const float*)d_in[22];
    float* out = (float*)d_out;

    float *A,*Bp,*Cp,*D,*E,*F,*G,*invQ,*invK,*attn,*M;
    cudaGetSymbolAddress((void**)&A,    g_bufA);
    cudaGetSymbolAddress((void**)&Bp,   g_bufB);
    cudaGetSymbolAddress((void**)&Cp,   g_bufC);
    cudaGetSymbolAddress((void**)&D,    g_bufD);
    cudaGetSymbolAddress((void**)&E,    g_bufE);
    cudaGetSymbolAddress((void**)&F,    g_bufF);
    cudaGetSymbolAddress((void**)&G,    g_bufG);
    cudaGetSymbolAddress((void**)&invQ, g_invQ);
    cudaGetSymbolAddress((void**)&invK, g_invK);
    cudaGetSymbolAddress((void**)&attn, g_attn);
    cudaGetSymbolAddress((void**)&M,    g_M);

    const int LA_SMEM = (3*64*200 + 32*200) * (int)sizeof(float);  // 179200 B
    cudaFuncSetAttribute(line_attn, cudaFuncAttributeMaxDynamicSharedMemorySize, LA_SMEM);

    const int PBLK = 256;
    const int PGRD = NPIX / PBLK;   // 576

    // ---- x1 = conv2(gelu(dw(pw(x)))) + conv0(x) ----
    conv1x1_nb<<<PGRD, PBLK>>>(x, pw_w, A);
    dwconv<<<NTOT/256, 256>>>(A, dw_w, dw_b, Bp);
    x1_fuse<<<PGRD, PBLK>>>(Bp, x, conv2_w, conv2_b, conv0_w, conv0_b, Cp);

    // ---- channel attention -> out1 (E) ----
    conv1x1_nb<<<PGRD, PBLK>>>(Cp, att_q_w, A);
    conv1x1_nb<<<PGRD, PBLK>>>(Cp, att_k_w, Bp);
    conv1x1_nb<<<PGRD, PBLK>>>(Cp, att_v_w, D);
    norm_kernel<<<dim3(Bb*Cc, 2), 256>>>(A, Bp, invQ, invK);
    zero_attn<<<(Bb*HEADS*32*32 + 255)/256, 256>>>(attn);
    attn_dot<<<dim3(Bb*HEADS, NSPLIT), dim3(32,32)>>>(A, Bp, attn);
    softmax_M<<<Bb*HEADS, 1024>>>(att_p_w, temp, attn, invQ, invK, M);
    conv1x1_batch<<<PGRD, PBLK>>>(D, M, E);

    // ---- row attention -> out2 (F) ----
    conv1x1_nb<<<PGRD, PBLK>>>(Cp, row_q_w, A);
    conv1x1_nb<<<PGRD, PBLK>>>(Cp, row_k_w, Bp);
    conv1x1_nb<<<PGRD, PBLK>>>(E,  row_v_w, D);
    line_attn<<<Bb*Hh, 256, LA_SMEM>>>(A, Bp, D, Cp, F, row_g, Ww, 1);

    // ---- col attention -> out3 (G) ----
    conv1x1_nb<<<PGRD, PBLK>>>(Cp, col_q_w, A);
    conv1x1_nb<<<PGRD, PBLK>>>(Cp, col_k_w, Bp);
    conv1x1_nb<<<PGRD, PBLK>>>(E,  col_v_w, D);
    line_attn<<<Bb*Ww, 256, LA_SMEM>>>(A, Bp, D, Cp, G, col_g, 1, Ww);

    // ---- fuse + gelu ----
    final_conv<<<PGRD, PBLK>>>(E, F, G, conv_w, conv_b, out);
}

// round 4
// speedup vs baseline: 1.1116x; 1.1116x over previous
#include <cuda_runtime.h>
#include <math.h>

#define Cc 64
#define Hh 192
#define Ww 192
#define HW (Hh*Ww)            // 36864
#define Bb 4
#define NPIX (Bb*HW)          // 147456
#define NTOT (Bb*Cc*HW)       // 9437184
#define NSPLIT 36
#define HEADS 2

// ---------------- scratch (static device memory; no allocs) ----------------
__device__ float g_bufA[NTOT];
__device__ float g_bufB[NTOT];
__device__ float g_bufC[NTOT];   // x1 (kept)
__device__ float g_bufD[NTOT];
__device__ float g_bufE[NTOT];   // out1 (kept)
__device__ float g_bufF[NTOT];   // out2
__device__ float g_bufG[NTOT];   // out3
__device__ float g_invQ[Bb*Cc];
__device__ float g_invK[Bb*Cc];
__device__ float g_attn[Bb*HEADS*32*32];
__device__ float g_M[Bb*Cc*Cc];

__device__ __forceinline__ float gelu_erf(float v){
    return 0.5f*v*(1.f+erff(v*0.70710678118654752f));
}

// ============= register-blocked 1x1 conv (no bias) =============
// thread: 4 consecutive pixels x 16 outputs. block: 256 threads = 256 pixels, 64 outputs.
__global__ void conv1x1_nb(const float* __restrict__ x, const float* __restrict__ w,
                           float* __restrict__ y){
    __shared__ float ws[64*64];  // ws[c*64+o]
    for (int idx = threadIdx.x; idx < 4096; idx += 256){
        int o = idx >> 6, c = idx & 63;
        ws[c*64 + o] = w[idx];
    }
    __syncthreads();
    int pg = threadIdx.x & 63, og = threadIdx.x >> 6;   // og 0..3
    int blockPix = blockIdx.x * 256;
    int b = blockPix / HW;
    int n0 = blockPix - b*HW + pg*4;
    const float4* xb = (const float4*)(x + (size_t)b*Cc*HW + n0);
    float4 acc[16];
    #pragma unroll
    for (int i=0;i<16;i++) acc[i] = make_float4(0.f,0.f,0.f,0.f);
    #pragma unroll 4
    for (int c=0;c<64;c++){
        float4 xv = xb[(size_t)c*(HW/4)];
        const float4* wr = (const float4*)(ws + c*64 + og*16);
        #pragma unroll
        for (int w4=0;w4<4;w4++){
            float4 wv = wr[w4];
            float4* a = acc + w4*4;
            a[0].x += wv.x*xv.x; a[0].y += wv.x*xv.y; a[0].z += wv.x*xv.z; a[0].w += wv.x*xv.w;
            a[1].x += wv.y*xv.x; a[1].y += wv.y*xv.y; a[1].z += wv.y*xv.z; a[1].w += wv.y*xv.w;
            a[2].x += wv.z*xv.x; a[2].y += wv.z*xv.y; a[2].z += wv.z*xv.z; a[2].w += wv.z*xv.w;
            a[3].x += wv.w*xv.x; a[3].y += wv.w*xv.y; a[3].z += wv.w*xv.z; a[3].w += wv.w*xv.w;
        }
    }
    float4* yb = (float4*)(y + (size_t)b*Cc*HW + n0);
    #pragma unroll
    for (int i=0;i<16;i++) yb[(size_t)(og*16+i)*(HW/4)] = acc[i];
}

// ============= same, per-batch weights (channel-attn out1 = M_b @ V) =============
__global__ void conv1x1_batch(const float* __restrict__ x, const float* __restrict__ wAll,
                              float* __restrict__ y){
    __shared__ float ws[64*64];
    int blockPix = blockIdx.x * 256;
    int b = blockPix / HW;
    const float* w = wAll + (size_t)b*4096;
    for (int idx = threadIdx.x; idx < 4096; idx += 256){
        int o = idx >> 6, c = idx & 63;
        ws[c*64 + o] = w[idx];
    }
    __syncthreads();
    int pg = threadIdx.x & 63, og = threadIdx.x >> 6;
    int n0 = blockPix - b*HW + pg*4;
    const float4* xb = (const float4*)(x + (size_t)b*Cc*HW + n0);
    float4 acc[16];
    #pragma unroll
    for (int i=0;i<16;i++) acc[i] = make_float4(0.f,0.f,0.f,0.f);
    #pragma unroll 4
    for (int c=0;c<64;c++){
        float4 xv = xb[(size_t)c*(HW/4)];
        const float4* wr = (const float4*)(ws + c*64 + og*16);
        #pragma unroll
        for (int w4=0;w4<4;w4++){
            float4 wv = wr[w4];
            float4* a = acc + w4*4;
            a[0].x += wv.x*xv.x; a[0].y += wv.x*xv.y; a[0].z += wv.x*xv.z; a[0].w += wv.x*xv.w;
            a[1].x += wv.y*xv.x; a[1].y += wv.y*xv.y; a[1].z += wv.y*xv.z; a[1].w += wv.y*xv.w;
            a[2].x += wv.z*xv.x; a[2].y += wv.z*xv.y; a[2].z += wv.z*xv.z; a[2].w += wv.z*xv.w;
            a[3].x += wv.w*xv.x; a[3].y += wv.w*xv.y; a[3].z += wv.w*xv.z; a[3].w += wv.w*xv.w;
        }
    }
    float4* yb = (float4*)(y + (size_t)b*Cc*HW + n0);
    #pragma unroll
    for (int i=0;i<16;i++) yb[(size_t)(og*16+i)*(HW/4)] = acc[i];
}

// ============= depthwise 3x3 + bias, fused GELU on the output =============
__global__ void dwconv(const float* __restrict__ x, const float* __restrict__ w,
                       const float* __restrict__ bias, float* __restrict__ y){
    int idx = blockIdx.x*256 + threadIdx.x;
    if (idx >= NTOT) return;
    int n  = idx % HW;
    int bc = idx / HW;
    int c  = bc & 63;
    int h = n / Ww, wc = n - h*Ww;
    const float* wp = w + c*9;
    float acc = bias[c];
    #pragma unroll
    for (int dy=-1;dy<=1;dy++){
        int hh = h + dy;
        if (hh < 0 || hh >= Hh) continue;
        #pragma unroll
        for (int dx=-1;dx<=1;dx++){
            int ww2 = wc + dx;
            if (ww2 < 0 || ww2 >= Ww) continue;
            acc += wp[(dy+1)*3 + (dx+1)] * x[idx + dy*Ww + dx];
        }
    }
    y[idx] = gelu_erf(acc);   // gelu folded here (t2 is pre-gelu'd)
}

// ============= x1 = conv2(g) + b2 + conv0(x) + b0, g already gelu'd =============
__global__ void x1_fuse(const float* __restrict__ g, const float* __restrict__ x,
                        const float* __restrict__ w2, const float* __restrict__ b2,
                        const float* __restrict__ w0, const float* __restrict__ b0,
                        float* __restrict__ y){
    __shared__ float ws2[4096], ws0[4096];
    for (int idx = threadIdx.x; idx < 4096; idx += 256){
        int o = idx >> 6, c = idx & 63;
        ws2[c*64+o] = w2[idx];
        ws0[c*64+o] = w0[idx];
    }
    __syncthreads();
    int pg = threadIdx.x & 63, og = threadIdx.x >> 6;
    int blockPix = blockIdx.x * 256;
    int b = blockPix / HW;
    int n0 = blockPix - b*HW + pg*4;
    const float4* gb = (const float4*)(g + (size_t)b*Cc*HW + n0);
    const float4* xb = (const float4*)(x + (size_t)b*Cc*HW + n0);
    float4 acc[16];
    #pragma unroll
    for (int i=0;i<16;i++){
        float bv = b2[og*16+i] + b0[og*16+i];
        acc[i] = make_float4(bv,bv,bv,bv);
    }
    #pragma unroll 2
    for (int c=0;c<64;c++){
        float4 gv = gb[(size_t)c*(HW/4)];
        float4 xv = xb[(size_t)c*(HW/4)];
        const float4* w2r = (const float4*)(ws2 + c*64 + og*16);
        const float4* w0r = (const float4*)(ws0 + c*64 + og*16);
        #pragma unroll
        for (int w4=0;w4<4;w4++){
            float4 a2 = w2r[w4], a0 = w0r[w4];
            float4* a = acc + w4*4;
            a[0].x += a2.x*gv.x + a0.x*xv.x; a[0].y += a2.x*gv.y + a0.x*xv.y;
            a[0].z += a2.x*gv.z + a0.x*xv.z; a[0].w += a2.x*gv.w + a0.x*xv.w;
            a[1].x += a2.y*gv.x + a0.y*xv.x; a[1].y += a2.y*gv.y + a0.y*xv.y;
            a[1].z += a2.y*gv.z + a0.y*xv.z; a[1].w += a2.y*gv.w + a0.y*xv.w;
            a[2].x += a2.z*gv.x + a0.z*xv.x; a[2].y += a2.z*gv.y + a0.z*xv.y;
            a[2].z += a2.z*gv.z + a0.z*xv.z; a[2].w += a2.z*gv.w + a0.z*xv.w;
            a[3].x += a2.w*gv.x + a0.w*xv.x; a[3].y += a2.w*gv.y + a0.w*xv.y;
            a[3].z += a2.w*gv.z + a0.w*xv.z; a[3].w += a2.w*gv.w + a0.w*xv.w;
        }
    }
    float4* yb = (float4*)(y + (size_t)b*Cc*HW + n0);
    #pragma unroll
    for (int i=0;i<16;i++) yb[(size_t)(og*16+i)*(HW/4)] = acc[i];
}

// ---------------- per-(b,channel) 1/max(||.||,1e-12) over HW, for Q and K
__global__ void norm_kernel(const float* __restrict__ Q, const float* __restrict__ K,
                            float* __restrict__ invQ, float* __restrict__ invK){
    const float* src = blockIdx.y ? K : Q;
    size_t base = (size_t)blockIdx.x * HW;
    float s = 0.f;
    for (int i = threadIdx.x; i < HW/4; i += 256){
        float4 v = ((const float4*)(src + base))[i];
        s += v.x*v.x + v.y*v.y + v.z*v.z + v.w*v.w;
    }
    #pragma unroll
    for (int o=16;o;o>>=1) s += __shfl_xor_sync(0xffffffffu, s, o);
    __shared__ float red[8];
    int warp = threadIdx.x >> 5, lane = threadIdx.x & 31;
    if (lane == 0) red[warp] = s;
    __syncthreads();
    if (threadIdx.x == 0){
        float t = 0.f;
        #pragma unroll
        for (int i=0;i<8;i++) t += red[i];
        float inv = 1.f / fmaxf(sqrtf(t), 1e-12f);
        (blockIdx.y ? invK : invQ)[blockIdx.x] = inv;
    }
}

__global__ void zero_attn(float* __restrict__ a){
    int i = blockIdx.x*256 + threadIdx.x;
    if (i < Bb*HEADS*32*32) a[i] = 0.f;
}

// ---------------- attn_raw[bg,c,d] += sum_n Q[c,n]K[d,n] over an n-chunk
__global__ void attn_dot(const float* __restrict__ Q, const float* __restrict__ K,
                         float* __restrict__ attn){
    __shared__ float Qs[32][33], Ks[32][33];
    int bg = blockIdx.x;               // 0..7 = b*2+g
    int b = bg >> 1, g = bg & 1;
    size_t base = ((size_t)b*Cc + g*32) * HW;
    int chunk = HW / NSPLIT;           // 1024
    int nstart = blockIdx.y * chunk;
    int c = threadIdx.y, d = threadIdx.x;
    float acc = 0.f;
    for (int n0 = nstart; n0 < nstart + chunk; n0 += 32){
        Qs[threadIdx.y][threadIdx.x] = Q[base + (size_t)threadIdx.y*HW + n0 + threadIdx.x];
        Ks[threadIdx.y][threadIdx.x] = K[base + (size_t)threadIdx.y*HW + n0 + threadIdx.x];
        __syncthreads();
        #pragma unroll
        for (int nn=0;nn<32;nn++) acc += Qs[c][nn]*Ks[d][nn];
        __syncthreads();
    }
    atomicAdd(&attn[(bg*32 + c)*32 + d], acc);
}

// ---------------- softmax on attn, then M_b[o, g*32+d] = sum_c proj[o,g*32+c]*attn[c,d]
__global__ void softmax_M(const float* __restrict__ proj, const float* __restrict__ temp,
                          const float* __restrict__ attn,
                          const float* __restrict__ invQ, const float* __restrict__ invK,
                          float* __restrict__ M){
    __shared__ float at[32][33];
    int bg = blockIdx.x, b = bg >> 1, g = bg & 1;
    int t = threadIdx.x;
    int w = t >> 5, lane = t & 31;
    float v = attn[(bg*32 + w)*32 + lane]
            * invQ[b*Cc + g*32 + w] * invK[b*Cc + g*32 + lane] * temp[g];
    float m = v;
    #pragma unroll
    for (int o=16;o;o>>=1) m = fmaxf(m, __shfl_xor_sync(0xffffffffu, m, o));
    v = __expf(v - m);
    float s = v;
    #pragma unroll
    for (int o=16;o;o>>=1) s += __shfl_xor_sync(0xffffffffu, s, o);
    at[w][lane] = v / s;
    __syncthreads();
    int o0 = t >> 5;
    float m0 = 0.f, m1 = 0.f;
    #pragma unroll 4
    for (int c2=0;c2<32;c2++){
        float a = at[c2][lane];
        m0 += __ldg(&proj[o0*Cc       + g*32 + c2]) * a;
        m1 += __ldg(&proj[(o0+32)*Cc  + g*32 + c2]) * a;
    }
    M[((size_t)b*Cc + o0     )*Cc + g*32 + lane] = m0;
    M[((size_t)b*Cc + o0 + 32)*Cc + g*32 + lane] = m1;
}

// ============= line attention: 512 threads, 64-row tiles, transposed V =============
// smem: Qs[64*200] Ks[64*200] Vt[192*68] st[64*193]  (204,032 B)
#define QKS 200
#define VTS 68
#define STS_ 193
__global__ void __launch_bounds__(512)
line_attn(const float* __restrict__ Q, const float* __restrict__ K,
          const float* __restrict__ V, const float* __restrict__ x1,
          float* __restrict__ out, const float* __restrict__ gamma_p,
          int lineStride, int posStride){
    extern __shared__ float sm[];
    float* Qs = sm;
    float* Ks = Qs + 64*QKS;
    float* Vt = Ks + 64*QKS;           // transposed: Vt[p*68 + c]
    float* st = Vt + 192*VTS;          // score tile [64][193]
    int b = blockIdx.x / 192;
    int line = blockIdx.x - b*192;
    size_t base = (size_t)b*Cc*HW + (size_t)line*lineStride;
    int t = threadIdx.x;

    // Load Q,K directly; V goes coalesced into st (linear), then transposed into Vt.
    for (int idx = t; idx < 64*192; idx += 512){
        int c = idx / 192, p = idx - c*192;
        size_t ga = base + (size_t)c*HW + (size_t)p*posStride;
        Qs[c*QKS+p] = Q[ga];
        Ks[c*QKS+p] = K[ga];
        st[c*STS_+p] = V[ga];
    }
    __syncthreads();
    for (int idx = t; idx < 64*192; idx += 512){
        int c = idx & 63, p = idx >> 6;            // lanes: consecutive c
        Vt[p*VTS + c] = st[c*STS_ + p];            // conflict-free both sides
    }
    float gamma = *gamma_p;
    __syncthreads();

    for (int i0 = 0; i0 < 192; i0 += 64){
        // --- score tile: rows i0..i0+63, cols 0..191 ---
        int ihalf = t >> 4;          // 0..31
        int jg = t & 15; int j0 = jg * 12;
        float acc0[12], acc1[12];
        #pragma unroll
        for (int jj=0;jj<12;jj++){ acc0[jj]=0.f; acc1[jj]=0.f; }
        #pragma unroll 4
        for (int c=0;c<64;c++){
            float q0 = Qs[c*QKS + i0 + ihalf];
            float q1 = Qs[c*QKS + i0 + ihalf + 32];
            const float4* kr = (const float4*)(&Ks[c*QKS + j0]);
            float4 k0 = kr[0], k1 = kr[1], k2 = kr[2];
            acc0[0]+=q0*k0.x; acc0[1]+=q0*k0.y; acc0[2]+=q0*k0.z; acc0[3]+=q0*k0.w;
            acc0[4]+=q0*k1.x; acc0[5]+=q0*k1.y; acc0[6]+=q0*k1.z; acc0[7]+=q0*k1.w;
            acc0[8]+=q0*k2.x; acc0[9]+=q0*k2.y; acc0[10]+=q0*k2.z; acc0[11]+=q0*k2.w;
            acc1[0]+=q1*k0.x; acc1[1]+=q1*k0.y; acc1[2]+=q1*k0.z; acc1[3]+=q1*k0.w;
            acc1[4]+=q1*k1.x; acc1[5]+=q1*k1.y; acc1[6]+=q1*k1.z; acc1[7]+=q1*k1.w;
            acc1[8]+=q1*k2.x; acc1[9]+=q1*k2.y; acc1[10]+=q1*k2.z; acc1[11]+=q1*k2.w;
        }
        #pragma unroll
        for (int jj=0;jj<12;jj++){
            st[ihalf*STS_ + j0 + jj]      = acc0[jj];
            st[(ihalf+32)*STS_ + j0 + jj] = acc1[jj];
        }
        __syncthreads();
        // --- softmax per row: 16 warps x 4 rows ---
        int warp = t >> 5, lane = t & 31;
        #pragma unroll
        for (int rr=0;rr<4;rr++){
            int r = warp + rr*16;
            float vals[6]; float mx = -3.4e38f;
            #pragma unroll
            for (int e=0;e<6;e++){ vals[e] = st[r*STS_ + lane + e*32]; mx = fmaxf(mx, vals[e]); }
            #pragma unroll
            for (int o=16;o;o>>=1) mx = fmaxf(mx, __shfl_xor_sync(0xffffffffu, mx, o));
            float sme = 0.f;
            #pragma unroll
            for (int e=0;e<6;e++){ vals[e] = __expf(vals[e]-mx); sme += vals[e]; }
            #pragma unroll
            for (int o=16;o;o>>=1) sme += __shfl_xor_sync(0xffffffffu, sme, o);
            float inv = 1.f/sme;
            #pragma unroll
            for (int e=0;e<6;e++) st[r*STS_ + lane + e*32] = vals[e]*inv;
        }
        __syncthreads();
        // --- out: thread = 1 row x 8 channels; a is conflict-free, V broadcast ---
        int ro = t & 63;                 // row within tile
        int c0 = (t >> 6) * 8;           // channel group (const per warp)
        float4 oa0 = make_float4(0.f,0.f,0.f,0.f);
        float4 oa1 = make_float4(0.f,0.f,0.f,0.f);
        const float* arow = st + ro*STS_;
        #pragma unroll 4
        for (int j=0;j<192;j++){
            float a = arow[j];
            const float4* vp = (const float4*)(&Vt[j*VTS + c0]);
            float4 v0 = vp[0], v1 = vp[1];
            oa0.x += a*v0.x; oa0.y += a*v0.y; oa0.z += a*v0.z; oa0.w += a*v0.w;
            oa1.x += a*v1.x; oa1.y += a*v1.y; oa1.z += a*v1.z; oa1.w += a*v1.w;
        }
        int i = i0 + ro;
        float res[8] = {oa0.x,oa0.y,oa0.z,oa0.w,oa1.x,oa1.y,oa1.z,oa1.w};
        #pragma unroll
        for (int k=0;k<8;k++){
            size_t ga = base + (size_t)(c0+k)*HW + (size_t)i*posStride;
            out[ga] = gamma*res[k] + x1[ga];
        }
        __syncthreads();
    }
}

// ============= final: gelu( Wf [out1;out2;out3] + bf ), register-blocked =============
__global__ void final_conv(const float* __restrict__ o1, const float* __restrict__ o2,
                           const float* __restrict__ o3, const float* __restrict__ w,
                           const float* __restrict__ bias, float* __restrict__ out){
    __shared__ float ws[192*64];  // ws[c*64+o], w layout [o][192]
    for (int idx = threadIdx.x; idx < 192*64; idx += 256){
        int o = idx / 192, c = idx - o*192;
        ws[c*64 + o] = w[idx];
    }
    __syncthreads();
    int pg = threadIdx.x & 63, og = threadIdx.x >> 6;
    int blockPix = blockIdx.x * 256;
    int b = blockPix / HW;
    int n0 = blockPix - b*HW + pg*4;
    size_t boff = (size_t)b*Cc*HW + n0;
    float4 acc[16];
    #pragma unroll
    for (int i=0;i<16;i++){
        float bv = bias[og*16+i];
        acc[i] = make_float4(bv,bv,bv,bv);
    }
    const float* srcs[3] = {o1, o2, o3};
    #pragma unroll
    for (int s3=0;s3<3;s3++){
        const float4* pb = (const float4*)(srcs[s3] + boff);
        #pragma unroll 4
        for (int c=0;c<64;c++){
            float4 xv = pb[(size_t)c*(HW/4)];
            const float4* wr = (const float4*)(ws + (s3*64+c)*64 + og*16);
            #pragma unroll
            for (int w4=0;w4<4;w4++){
                float4 wv = wr[w4];
                float4* a = acc + w4*4;
                a[0].x += wv.x*xv.x; a[0].y += wv.x*xv.y; a[0].z += wv.x*xv.z; a[0].w += wv.x*xv.w;
                a[1].x += wv.y*xv.x; a[1].y += wv.y*xv.y; a[1].z += wv.y*xv.z; a[1].w += wv.y*xv.w;
                a[2].x += wv.z*xv.x; a[2].y += wv.z*xv.y; a[2].z += wv.z*xv.z; a[2].w += wv.z*xv.w;
                a[3].x += wv.w*xv.x; a[3].y += wv.w*xv.y; a[3].z += wv.w*xv.z; a[3].w += wv.w*xv.w;
            }
        }
    }
    float4* yb = (float4*)(out + boff);
    #pragma unroll
    for (int i=0;i<16;i++){
        float4 v = acc[i];
        v.x = gelu_erf(v.x); v.y = gelu_erf(v.y); v.z = gelu_erf(v.z); v.w = gelu_erf(v.w);
        yb[(size_t)(og*16+i)*(HW/4)] = v;
    }
}

// =====================================================================
extern "C" void kernel_launch(void* const* d_in, const int* in_sizes, int n_in,
                              void* d_out, int out_size){
    (void)in_sizes; (void)n_in; (void)out_size;
    const float* x        = (const float*)d_in[0];
    const float* pw_w     = (const float*)d_in[1];
    const float* dw_w     = (const float*)d_in[2];
    const float* dw_b     = (const float*)d_in[3];
    const float* conv2_w  = (const float*)d_in[4];
    const float* conv2_b  = (const float*)d_in[5];
    const float* conv0_w  = (const float*)d_in[6];
    const float* conv0_b  = (const float*)d_in[7];
    const float* att_q_w  = (const float*)d_in[8];
    const float* att_k_w  = (const float*)d_in[9];
    const float* att_v_w  = (const float*)d_in[10];
    const float* att_p_w  = (const float*)d_in[11];
    const float* temp     = (const float*)d_in[12];
    const float* row_q_w  = (const float*)d_in[13];
    const float* row_k_w  = (const float*)d_in[14];
    const float* row_v_w  = (const float*)d_in[15];
    const float* row_g    = (const float*)d_in[16];
    const float* col_q_w  = (const float*)d_in[17];
    const float* col_k_w  = (const float*)d_in[18];
    const float* col_v_w  = (const float*)d_in[19];
    const float* col_g    = (const float*)d_in[20];
    const float* conv_w   = (const float*)d_in[21];
    const float* conv_b   = (const float*)d_in[22];
    float* out = (float*)d_out;

    float *A,*Bp,*Cp,*D,*E,*F,*G,*invQ,*invK,*attn,*M;
    cudaGetSymbolAddress((void**)&A,    g_bufA);
    cudaGetSymbolAddress((void**)&Bp,   g_bufB);
    cudaGetSymbolAddress((void**)&Cp,   g_bufC);
    cudaGetSymbolAddress((void**)&D,    g_bufD);
    cudaGetSymbolAddress((void**)&E,    g_bufE);
    cudaGetSymbolAddress((void**)&F,    g_bufF);
    cudaGetSymbolAddress((void**)&G,    g_bufG);
    cudaGetSymbolAddress((void**)&invQ, g_invQ);
    cudaGetSymbolAddress((void**)&invK, g_invK);
    cudaGetSymbolAddress((void**)&attn, g_attn);
    cudaGetSymbolAddress((void**)&M,    g_M);

    const int LA_SMEM = (64*QKS + 64*QKS + 192*VTS + 64*STS_) * (int)sizeof(float); // 204032
    cudaFuncSetAttribute(line_attn, cudaFuncAttributeMaxDynamicSharedMemorySize, LA_SMEM);

    const int PBLK = 256;
    const int PGRD = NPIX / PBLK;   // 576

    // ---- x1 = conv2(gelu(dw(pw(x)))) + conv0(x) ----
    conv1x1_nb<<<PGRD, PBLK>>>(x, pw_w, A);
    dwconv<<<NTOT/256, 256>>>(A, dw_w, dw_b, Bp);      // emits gelu(dw out)
    x1_fuse<<<PGRD, PBLK>>>(Bp, x, conv2_w, conv2_b, conv0_w, conv0_b, Cp);

    // ---- channel attention -> out1 (E) ----
    conv1x1_nb<<<PGRD, PBLK>>>(Cp, att_q_w, A);
    conv1x1_nb<<<PGRD, PBLK>>>(Cp, att_k_w, Bp);
    conv1x1_nb<<<PGRD, PBLK>>>(Cp, att_v_w, D);
    norm_kernel<<<dim3(Bb*Cc, 2), 256>>>(A, Bp, invQ, invK);
    zero_attn<<<(Bb*HEADS*32*32 + 255)/256, 256>>>(attn);
    attn_dot<<<dim3(Bb*HEADS, NSPLIT), dim3(32,32)>>>(A, Bp, attn);
    softmax_M<<<Bb*HEADS, 1024>>>(att_p_w, temp, attn, invQ, invK, M);
    conv1x1_batch<<<PGRD, PBLK>>>(D, M, E);

    // ---- row attention -> out2 (F) ----
    conv1x1_nb<<<PGRD, PBLK>>>(Cp, row_q_w, A);
    conv1x1_nb<<<PGRD, PBLK>>>(Cp, row_k_w, Bp);
    conv1x1_nb<<<PGRD, PBLK>>>(E,  row_v_w, D);
    line_attn<<<Bb*Hh, 512, LA_SMEM>>>(A, Bp, D, Cp, F, row_g, Ww, 1);

    // ---- col attention -> out3 (G) ----
    conv1x1_nb<<<PGRD, PBLK>>>(Cp, col_q_w, A);
    conv1x1_nb<<<PGRD, PBLK>>>(Cp, col_k_w, Bp);
    conv1x1_nb<<<PGRD, PBLK>>>(E,  col_v_w, D);
    line_attn<<<Bb*Ww, 512, LA_SMEM>>>(A, Bp, D, Cp, G, col_g, 1, Ww);

    // ---- fuse + gelu ----
    final_conv<<<PGRD, PBLK>>>(E, F, G, conv_w, conv_b, out);
}

// round 8
// speedup vs baseline: 1.1511x; 1.0355x over previous
#include <cuda_runtime.h>
#include <math.h>

#define Cc 64
#define Hh 192
#define Ww 192
#define HW (Hh*Ww)            // 36864
#define Bb 4
#define NPIX (Bb*HW)          // 147456
#define NTOT (Bb*Cc*HW)       // 9437184
#define NSPLIT 36
#define HEADS 2

typedef unsigned long long u64c;

// ---------------- scratch (static device memory; no allocs) ----------------
__device__ float g_bufA[NTOT];
__device__ float g_bufB[NTOT];
__device__ float g_bufC[NTOT];   // x1 (kept)
__device__ float g_bufD[NTOT];
__device__ float g_bufE[NTOT];   // out1 (kept)
__device__ float g_bufF[NTOT];   // out2
__device__ float g_bufG[NTOT];   // out3
__device__ float g_invQ[Bb*Cc];
__device__ float g_invK[Bb*Cc];
__device__ float g_attn[Bb*HEADS*32*32];
__device__ float g_M[Bb*Cc*Cc];

__device__ __forceinline__ float gelu_erf(float v){
    return 0.5f*v*(1.f+erff(v*0.70710678118654752f));
}
__device__ __forceinline__ u64c pack2(float lo, float hi){
    u64c r; asm("mov.b64 %0, {%1, %2};" : "=l"(r) : "f"(lo), "f"(hi)); return r;
}
__device__ __forceinline__ u64c ffma2(u64c a, u64c b, u64c c){
    u64c d; asm("fma.rn.f32x2 %0, %1, %2, %3;" : "=l"(d) : "l"(a), "l"(b), "l"(c)); return d;
}
__device__ __forceinline__ float2 unpack2(u64c v){
    float2 f; asm("mov.b64 {%0, %1}, %2;" : "=f"(f.x), "=f"(f.y) : "l"(v)); return f;
}

// NOTE: ulonglong2 = 16 bytes = 4 floats. Channel stride HW floats = HW/4 ulonglong2.
#define CH_STRIDE_U2 (HW/4)

// ============= register-blocked 1x1 conv (no bias), f32x2 =============
// thread: 4 pixels x 16 outputs. block: 256 threads = 256 pixels, 64 outputs.
__global__ void __launch_bounds__(256, 2)
conv1x1_nb(const float* __restrict__ x, const float* __restrict__ w,
           float* __restrict__ y){
    __shared__ u64c ws[64*64];  // ws[c*64+o] = {w[o][c], w[o][c]}  (32KB)
    for (int idx = threadIdx.x; idx < 4096; idx += 256){
        int o = idx >> 6, c = idx & 63;
        float wv = w[idx];
        ws[c*64 + o] = pack2(wv, wv);
    }
    __syncthreads();
    int pg = threadIdx.x & 63, og = threadIdx.x >> 6;   // og 0..3
    int blockPix = blockIdx.x * 256;
    int b = blockPix / HW;
    int n0 = blockPix - b*HW + pg*4;
    const ulonglong2* xb = (const ulonglong2*)(x + (size_t)b*Cc*HW + n0);
    u64c acc[16][2];
    #pragma unroll
    for (int i=0;i<16;i++){ acc[i][0]=0ull; acc[i][1]=0ull; }
    #pragma unroll 4
    for (int c=0;c<64;c++){
        ulonglong2 xv = xb[(size_t)c*CH_STRIDE_U2];      // 4 pixels = 2 f32x2
        const ulonglong2* wr = (const ulonglong2*)(ws + c*64 + og*16);
        #pragma unroll
        for (int k=0;k<8;k++){
            ulonglong2 wp = wr[k];                       // broadcast LDS.128
            acc[2*k  ][0] = ffma2(wp.x, xv.x, acc[2*k  ][0]);
            acc[2*k  ][1] = ffma2(wp.x, xv.y, acc[2*k  ][1]);
            acc[2*k+1][0] = ffma2(wp.y, xv.x, acc[2*k+1][0]);
            acc[2*k+1][1] = ffma2(wp.y, xv.y, acc[2*k+1][1]);
        }
    }
    ulonglong2* yb = (ulonglong2*)(y + (size_t)b*Cc*HW + n0);
    #pragma unroll
    for (int i=0;i<16;i++){
        ulonglong2 v; v.x = acc[i][0]; v.y = acc[i][1];
        yb[(size_t)(og*16+i)*CH_STRIDE_U2] = v;
    }
}

// ============= same, per-batch weights (channel-attn out1 = M_b @ V) =============
__global__ void __launch_bounds__(256, 2)
conv1x1_batch(const float* __restrict__ x, const float* __restrict__ wAll,
              float* __restrict__ y){
    __shared__ u64c ws[64*64];
    int blockPix = blockIdx.x * 256;
    int b = blockPix / HW;
    const float* w = wAll + (size_t)b*4096;
    for (int idx = threadIdx.x; idx < 4096; idx += 256){
        int o = idx >> 6, c = idx & 63;
        float wv = w[idx];
        ws[c*64 + o] = pack2(wv, wv);
    }
    __syncthreads();
    int pg = threadIdx.x & 63, og = threadIdx.x >> 6;
    int n0 = blockPix - b*HW + pg*4;
    const ulonglong2* xb = (const ulonglong2*)(x + (size_t)b*Cc*HW + n0);
    u64c acc[16][2];
    #pragma unroll
    for (int i=0;i<16;i++){ acc[i][0]=0ull; acc[i][1]=0ull; }
    #pragma unroll 4
    for (int c=0;c<64;c++){
        ulonglong2 xv = xb[(size_t)c*CH_STRIDE_U2];
        const ulonglong2* wr = (const ulonglong2*)(ws + c*64 + og*16);
        #pragma unroll
        for (int k=0;k<8;k++){
            ulonglong2 wp = wr[k];
            acc[2*k  ][0] = ffma2(wp.x, xv.x, acc[2*k  ][0]);
            acc[2*k  ][1] = ffma2(wp.x, xv.y, acc[2*k  ][1]);
            acc[2*k+1][0] = ffma2(wp.y, xv.x, acc[2*k+1][0]);
            acc[2*k+1][1] = ffma2(wp.y, xv.y, acc[2*k+1][1]);
        }
    }
    ulonglong2* yb = (ulonglong2*)(y + (size_t)b*Cc*HW + n0);
    #pragma unroll
    for (int i=0;i<16;i++){
        ulonglong2 v; v.x = acc[i][0]; v.y = acc[i][1];
        yb[(size_t)(og*16+i)*CH_STRIDE_U2] = v;
    }
}

// ============= depthwise 3x3 + bias, fused GELU =============
__global__ void dwconv(const float* __restrict__ x, const float* __restrict__ w,
                       const float* __restrict__ bias, float* __restrict__ y){
    int idx = blockIdx.x*256 + threadIdx.x;
    if (idx >= NTOT) return;
    int n  = idx % HW;
    int bc = idx / HW;
    int c  = bc & 63;
    int h = n / Ww, wc = n - h*Ww;
    const float* wp = w + c*9;
    float acc = bias[c];
    #pragma unroll
    for (int dy=-1;dy<=1;dy++){
        int hh = h + dy;
        if (hh < 0 || hh >= Hh) continue;
        #pragma unroll
        for (int dx=-1;dx<=1;dx++){
            int ww2 = wc + dx;
            if (ww2 < 0 || ww2 >= Ww) continue;
            acc += wp[(dy+1)*3 + (dx+1)] * x[idx + dy*Ww + dx];
        }
    }
    y[idx] = gelu_erf(acc);
}

// ============= x1 = conv2(g) + b2 + conv0(x) + b0, g already gelu'd, f32x2 =============
__global__ void __launch_bounds__(256, 2)
x1_fuse(const float* __restrict__ g, const float* __restrict__ x,
        const float* __restrict__ w2, const float* __restrict__ b2,
        const float* __restrict__ w0, const float* __restrict__ b0,
        float* __restrict__ y){
    extern __shared__ u64c sm2[];
    u64c* ws2 = sm2;          // 4096 u64 = 32KB
    u64c* ws0 = sm2 + 4096;   // 32KB
    for (int idx = threadIdx.x; idx < 4096; idx += 256){
        int o = idx >> 6, c = idx & 63;
        float a2 = w2[idx], a0 = w0[idx];
        ws2[c*64+o] = pack2(a2, a2);
        ws0[c*64+o] = pack2(a0, a0);
    }
    __syncthreads();
    int pg = threadIdx.x & 63, og = threadIdx.x >> 6;
    int blockPix = blockIdx.x * 256;
    int b = blockPix / HW;
    int n0 = blockPix - b*HW + pg*4;
    const ulonglong2* gb = (const ulonglong2*)(g + (size_t)b*Cc*HW + n0);
    const ulonglong2* xb = (const ulonglong2*)(x + (size_t)b*Cc*HW + n0);
    u64c acc[16][2];
    #pragma unroll
    for (int i=0;i<16;i++){
        float bv = b2[og*16+i] + b0[og*16+i];
        u64c p = pack2(bv,bv);
        acc[i][0]=p; acc[i][1]=p;
    }
    #pragma unroll 2
    for (int c=0;c<64;c++){
        ulonglong2 gv = gb[(size_t)c*CH_STRIDE_U2];
        ulonglong2 xv = xb[(size_t)c*CH_STRIDE_U2];
        const ulonglong2* w2r = (const ulonglong2*)(ws2 + c*64 + og*16);
        const ulonglong2* w0r = (const ulonglong2*)(ws0 + c*64 + og*16);
        #pragma unroll
        for (int k=0;k<8;k++){
            ulonglong2 a2 = w2r[k], a0 = w0r[k];
            acc[2*k  ][0] = ffma2(a2.x, gv.x, acc[2*k  ][0]);
            acc[2*k  ][1] = ffma2(a2.x, gv.y, acc[2*k  ][1]);
            acc[2*k+1][0] = ffma2(a2.y, gv.x, acc[2*k+1][0]);
            acc[2*k+1][1] = ffma2(a2.y, gv.y, acc[2*k+1][1]);
            acc[2*k  ][0] = ffma2(a0.x, xv.x, acc[2*k  ][0]);
            acc[2*k  ][1] = ffma2(a0.x, xv.y, acc[2*k  ][1]);
            acc[2*k+1][0] = ffma2(a0.y, xv.x, acc[2*k+1][0]);
            acc[2*k+1][1] = ffma2(a0.y, xv.y, acc[2*k+1][1]);
        }
    }
    ulonglong2* yb = (ulonglong2*)(y + (size_t)b*Cc*HW + n0);
    #pragma unroll
    for (int i=0;i<16;i++){
        ulonglong2 v; v.x = acc[i][0]; v.y = acc[i][1];
        yb[(size_t)(og*16+i)*CH_STRIDE_U2] = v;
    }
}

// ---------------- per-(b,channel) 1/max(||.||,1e-12) over HW, for Q and K
__global__ void norm_kernel(const float* __restrict__ Q, const float* __restrict__ K,
                            float* __restrict__ invQ, float* __restrict__ invK){
    const float* src = blockIdx.y ? K : Q;
    size_t base = (size_t)blockIdx.x * HW;
    float s = 0.f;
    for (int i = threadIdx.x; i < HW/4; i += 256){
        float4 v = ((const float4*)(src + base))[i];
        s += v.x*v.x + v.y*v.y + v.z*v.z + v.w*v.w;
    }
    #pragma unroll
    for (int o=16;o;o>>=1) s += __shfl_xor_sync(0xffffffffu, s, o);
    __shared__ float red[8];
    int warp = threadIdx.x >> 5, lane = threadIdx.x & 31;
    if (lane == 0) red[warp] = s;
    __syncthreads();
    if (threadIdx.x == 0){
        float t = 0.f;
        #pragma unroll
        for (int i=0;i<8;i++) t += red[i];
        float inv = 1.f / fmaxf(sqrtf(t), 1e-12f);
        (blockIdx.y ? invK : invQ)[blockIdx.x] = inv;
    }
}

__global__ void zero_attn(float* __restrict__ a){
    int i = blockIdx.x*256 + threadIdx.x;
    if (i < Bb*HEADS*32*32) a[i] = 0.f;
}

// ---------------- attn_raw[bg,c,d] += sum_n Q[c,n]K[d,n] over an n-chunk
__global__ void attn_dot(const float* __restrict__ Q, const float* __restrict__ K,
                         float* __restrict__ attn){
    __shared__ float Qs[32][33], Ks[32][33];
    int bg = blockIdx.x;
    int b = bg >> 1, g = bg & 1;
    size_t base = ((size_t)b*Cc + g*32) * HW;
    int chunk = HW / NSPLIT;           // 1024
    int nstart = blockIdx.y * chunk;
    int c = threadIdx.y, d = threadIdx.x;
    float acc = 0.f;
    for (int n0 = nstart; n0 < nstart + chunk; n0 += 32){
        Qs[threadIdx.y][threadIdx.x] = Q[base + (size_t)threadIdx.y*HW + n0 + threadIdx.x];
        Ks[threadIdx.y][threadIdx.x] = K[base + (size_t)threadIdx.y*HW + n0 + threadIdx.x];
        __syncthreads();
        #pragma unroll
        for (int nn=0;nn<32;nn++) acc += Qs[c][nn]*Ks[d][nn];
        __syncthreads();
    }
    atomicAdd(&attn[(bg*32 + c)*32 + d], acc);
}

// ---------------- softmax on attn, then M_b[o, g*32+d] = sum_c proj[o,g*32+c]*attn[c,d]
__global__ void softmax_M(const float* __restrict__ proj, const float* __restrict__ temp,
                          const float* __restrict__ attn,
                          const float* __restrict__ invQ, const float* __restrict__ invK,
                          float* __restrict__ M){
    __shared__ float at[32][33];
    int bg = blockIdx.x, b = bg >> 1, g = bg & 1;
    int t = threadIdx.x;
    int w = t >> 5, lane = t & 31;
    float v = attn[(bg*32 + w)*32 + lane]
            * invQ[b*Cc + g*32 + w] * invK[b*Cc + g*32 + lane] * temp[g];
    float m = v;
    #pragma unroll
    for (int o=16;o;o>>=1) m = fmaxf(m, __shfl_xor_sync(0xffffffffu, m, o));
    v = __expf(v - m);
    float s = v;
    #pragma unroll
    for (int o=16;o;o>>=1) s += __shfl_xor_sync(0xffffffffu, s, o);
    at[w][lane] = v / s;
    __syncthreads();
    int o0 = t >> 5;
    float m0 = 0.f, m1 = 0.f;
    #pragma unroll 4
    for (int c2=0;c2<32;c2++){
        float a = at[c2][lane];
        m0 += __ldg(&proj[o0*Cc       + g*32 + c2]) * a;
        m1 += __ldg(&proj[(o0+32)*Cc  + g*32 + c2]) * a;
    }
    M[((size_t)b*Cc + o0     )*Cc + g*32 + lane] = m0;
    M[((size_t)b*Cc + o0 + 32)*Cc + g*32 + lane] = m1;
}

// ============= line attention: 512 threads, 64-row tiles, f32x2 =============
#define QKS 200
#define VTS 68
#define STS_ 193
__global__ void __launch_bounds__(512)
line_attn(const float* __restrict__ Q, const float* __restrict__ K,
          const float* __restrict__ V, const float* __restrict__ x1,
          float* __restrict__ out, const float* __restrict__ gamma_p,
          int lineStride, int posStride){
    extern __shared__ float sm[];
    float* Qs = sm;
    float* Ks = Qs + 64*QKS;
    float* Vt = Ks + 64*QKS;           // transposed: Vt[p*68 + c]
    float* st = Vt + 192*VTS;          // score tile [64][193]
    int b = blockIdx.x / 192;
    int line = blockIdx.x - b*192;
    size_t base = (size_t)b*Cc*HW + (size_t)line*lineStride;
    int t = threadIdx.x;

    for (int idx = t; idx < 64*192; idx += 512){
        int c = idx / 192, p = idx - c*192;
        size_t ga = base + (size_t)c*HW + (size_t)p*posStride;
        Qs[c*QKS+p] = Q[ga];
        Ks[c*QKS+p] = K[ga];
        st[c*STS_+p] = V[ga];
    }
    __syncthreads();
    for (int idx = t; idx < 64*192; idx += 512){
        int c = idx & 63, p = idx >> 6;
        Vt[p*VTS + c] = st[c*STS_ + p];
    }
    float gamma = *gamma_p;
    __syncthreads();

    for (int i0 = 0; i0 < 192; i0 += 64){
        // --- score tile: rows i0..i0+63; thread: 2 rows x 12 cols (3 chunks of 4) ---
        int ihalf = t >> 4;           // 0..31
        int jg = t & 15;              // chunk base jg*4 + {0,64,128}: lanes->contiguous
        u64c acc0[6], acc1[6];
        #pragma unroll
        for (int z=0;z<6;z++){ acc0[z]=0ull; acc1[z]=0ull; }
        #pragma unroll 4
        for (int c=0;c<64;c++){
            float q0 = Qs[c*QKS + i0 + ihalf];
            float q1 = Qs[c*QKS + i0 + ihalf + 32];
            u64c q0d = pack2(q0,q0), q1d = pack2(q1,q1);
            #pragma unroll
            for (int ch=0; ch<3; ch++){
                ulonglong2 kp = *(const ulonglong2*)(&Ks[c*QKS + jg*4 + ch*64]);
                acc0[2*ch  ] = ffma2(q0d, kp.x, acc0[2*ch  ]);
                acc0[2*ch+1] = ffma2(q0d, kp.y, acc0[2*ch+1]);
                acc1[2*ch  ] = ffma2(q1d, kp.x, acc1[2*ch  ]);
                acc1[2*ch+1] = ffma2(q1d, kp.y, acc1[2*ch+1]);
            }
        }
        #pragma unroll
        for (int ch=0; ch<3; ch++){
            #pragma unroll
            for (int p2=0;p2<2;p2++){
                float2 v0 = unpack2(acc0[2*ch+p2]);
                float2 v1 = unpack2(acc1[2*ch+p2]);
                int col = jg*4 + ch*64 + p2*2;
                st[ihalf*STS_ + col]        = v0.x;
                st[ihalf*STS_ + col + 1]    = v0.y;
                st[(ihalf+32)*STS_ + col]   = v1.x;
                st[(ihalf+32)*STS_ + col+1] = v1.y;
            }
        }
        __syncthreads();
        // --- softmax per row: 16 warps x 4 rows ---
        int warp = t >> 5, lane = t & 31;
        #pragma unroll
        for (int rr=0;rr<4;rr++){
            int r = warp + rr*16;
            float vals[6]; float mx = -3.4e38f;
            #pragma unroll
            for (int e=0;e<6;e++){ vals[e] = st[r*STS_ + lane + e*32]; mx = fmaxf(mx, vals[e]); }
            #pragma unroll
            for (int o=16;o;o>>=1) mx = fmaxf(mx, __shfl_xor_sync(0xffffffffu, mx, o));
            float sme = 0.f;
            #pragma unroll
            for (int e=0;e<6;e++){ vals[e] = __expf(vals[e]-mx); sme += vals[e]; }
            #pragma unroll
            for (int o=16;o;o>>=1) sme += __shfl_xor_sync(0xffffffffu, sme, o);
            float inv = 1.f/sme;
            #pragma unroll
            for (int e=0;e<6;e++) st[r*STS_ + lane + e*32] = vals[e]*inv;
        }
        __syncthreads();
        // --- out: thread = 1 row x 8 channels (4 f32x2 pairs) ---
        int ro = t & 63;
        int c0 = (t >> 6) * 8;
        u64c oa[4];
        #pragma unroll
        for (int z=0;z<4;z++) oa[z]=0ull;
        const float* arow = st + ro*STS_;
        #pragma unroll 4
        for (int j=0;j<192;j++){
            float a = arow[j];
            u64c ad = pack2(a,a);
            ulonglong2 v01 = *(const ulonglong2*)(&Vt[j*VTS + c0]);
            ulonglong2 v23 = *(const ulonglong2*)(&Vt[j*VTS + c0 + 4]);
            oa[0] = ffma2(ad, v01.x, oa[0]);
            oa[1] = ffma2(ad, v01.y, oa[1]);
            oa[2] = ffma2(ad, v23.x, oa[2]);
            oa[3] = ffma2(ad, v23.y, oa[3]);
        }
        int i = i0 + ro;
        float res[8];
        #pragma unroll
        for (int z=0;z<4;z++){
            float2 v = unpack2(oa[z]);
            res[2*z] = v.x; res[2*z+1] = v.y;
        }
        #pragma unroll
        for (int k=0;k<8;k++){
            size_t ga = base + (size_t)(c0+k)*HW + (size_t)i*posStride;
            out[ga] = gamma*res[k] + x1[ga];
        }
        __syncthreads();
    }
}

// ============= final: gelu( Wf [out1;out2;out3] + bf ), f32x2 =============
__global__ void __launch_bounds__(256, 2)
final_conv(const float* __restrict__ o1, const float* __restrict__ o2,
           const float* __restrict__ o3, const float* __restrict__ w,
           const float* __restrict__ bias, float* __restrict__ out){
    extern __shared__ u64c ws[];   // [192*64] u64 = 96KB; ws[c3*64+o] duplicated
    for (int idx = threadIdx.x; idx < 192*64; idx += 256){
        int o = idx / 192, c = idx - o*192;
        float wv = w[idx];
        ws[c*64 + o] = pack2(wv, wv);
    }
    __syncthreads();
    int pg = threadIdx.x & 63, og = threadIdx.x >> 6;
    int blockPix = blockIdx.x * 256;
    int b = blockPix / HW;
    int n0 = blockPix - b*HW + pg*4;
    size_t boff = (size_t)b*Cc*HW + n0;
    u64c acc[16][2];
    #pragma unroll
    for (int i=0;i<16;i++){
        float bv = bias[og*16+i];
        u64c p = pack2(bv,bv);
        acc[i][0]=p; acc[i][1]=p;
    }
    const float* srcs[3] = {o1, o2, o3};
    #pragma unroll
    for (int s3=0;s3<3;s3++){
        const ulonglong2* pb = (const ulonglong2*)(srcs[s3] + boff);
        #pragma unroll 4
        for (int c=0;c<64;c++){
            ulonglong2 xv = pb[(size_t)c*CH_STRIDE_U2];
            const ulonglong2* wr = (const ulonglong2*)(ws + (s3*64+c)*64 + og*16);
            #pragma unroll
            for (int k=0;k<8;k++){
                ulonglong2 wp = wr[k];
                acc[2*k  ][0] = ffma2(wp.x, xv.x, acc[2*k  ][0]);
                acc[2*k  ][1] = ffma2(wp.x, xv.y, acc[2*k  ][1]);
                acc[2*k+1][0] = ffma2(wp.y, xv.x, acc[2*k+1][0]);
                acc[2*k+1][1] = ffma2(wp.y, xv.y, acc[2*k+1][1]);
            }
        }
    }
    float* yb = out + boff;
    #pragma unroll
    for (int i=0;i<16;i++){
        float2 a = unpack2(acc[i][0]);
        float2 bq = unpack2(acc[i][1]);
        float4 v;
        v.x = gelu_erf(a.x); v.y = gelu_erf(a.y);
        v.z = gelu_erf(bq.x); v.w = gelu_erf(bq.y);
        *((float4*)(yb + (size_t)(og*16+i)*HW)) = v;
    }
}

// =====================================================================
extern "C" void kernel_launch(void* const* d_in, const int* in_sizes, int n_in,
                              void* d_out, int out_size){
    (void)in_sizes; (void)n_in; (void)out_size;
    const float* x        = (const float*)d_in[0];
    const float* pw_w     = (const float*)d_in[1];
    const float* dw_w     = (const float*)d_in[2];
    const float* dw_b     = (const float*)d_in[3];
    const float* conv2_w  = (const float*)d_in[4];
    const float* conv2_b  = (const float*)d_in[5];
    const float* conv0_w  = (const float*)d_in[6];
    const float* conv0_b  = (const float*)d_in[7];
    const float* att_q_w  = (const float*)d_in[8];
    const float* att_k_w  = (const float*)d_in[9];
    const float* att_v_w  = (const float*)d_in[10];
    const float* att_p_w  = (const float*)d_in[11];
    const float* temp     = (const float*)d_in[12];
    const float* row_q_w  = (const float*)d_in[13];
    const float* row_k_w  = (const float*)d_in[14];
    const float* row_v_w  = (const float*)d_in[15];
    const float* row_g    = (const float*)d_in[16];
    const float* col_q_w  = (const float*)d_in[17];
    const float* col_k_w  = (const float*)d_in[18];
    const float* col_v_w  = (const float*)d_in[19];
    const float* col_g    = (const float*)d_in[20];
    const float* conv_w   = (const float*)d_in[21];
    const float* conv_b   = (const float*)d_in[22];
    float* out = (float*)d_out;

    float *A,*Bp,*Cp,*D,*E,*F,*G,*invQ,*invK,*attn,*M;
    cudaGetSymbolAddress((void**)&A,    g_bufA);
    cudaGetSymbolAddress((void**)&Bp,   g_bufB);
    cudaGetSymbolAddress((void**)&Cp,   g_bufC);
    cudaGetSymbolAddress((void**)&D,    g_bufD);
    cudaGetSymbolAddress((void**)&E,    g_bufE);
    cudaGetSymbolAddress((void**)&F,    g_bufF);
    cudaGetSymbolAddress((void**)&G,    g_bufG);
    cudaGetSymbolAddress((void**)&invQ, g_invQ);
    cudaGetSymbolAddress((void**)&invK, g_invK);
    cudaGetSymbolAddress((void**)&attn, g_attn);
    cudaGetSymbolAddress((void**)&M,    g_M);

    const int LA_SMEM = (64*QKS + 64*QKS + 192*VTS + 64*STS_) * (int)sizeof(float); // 204032
    cudaFuncSetAttribute(line_attn, cudaFuncAttributeMaxDynamicSharedMemorySize, LA_SMEM);
    const int XF_SMEM = 2*4096*(int)sizeof(u64c);   // 65536
    cudaFuncSetAttribute(x1_fuse, cudaFuncAttributeMaxDynamicSharedMemorySize, XF_SMEM);
    const int FC_SMEM = 192*64*(int)sizeof(u64c);   // 98304
    cudaFuncSetAttribute(final_conv, cudaFuncAttributeMaxDynamicSharedMemorySize, FC_SMEM);

    const int PBLK = 256;
    const int PGRD = NPIX / PBLK;   // 576

    // ---- x1 = conv2(gelu(dw(pw(x)))) + conv0(x) ----
    conv1x1_nb<<<PGRD, PBLK>>>(x, pw_w, A);
    dwconv<<<NTOT/256, 256>>>(A, dw_w, dw_b, Bp);      // emits gelu(dw out)
    x1_fuse<<<PGRD, PBLK, XF_SMEM>>>(Bp, x, conv2_w, conv2_b, conv0_w, conv0_b, Cp);

    // ---- channel attention -> out1 (E) ----
    conv1x1_nb<<<PGRD, PBLK>>>(Cp, att_q_w, A);
    conv1x1_nb<<<PGRD, PBLK>>>(Cp, att_k_w, Bp);
    conv1x1_nb<<<PGRD, PBLK>>>(Cp, att_v_w, D);
    norm_kernel<<<dim3(Bb*Cc, 2), 256>>>(A, Bp, invQ, invK);
    zero_attn<<<(Bb*HEADS*32*32 + 255)/256, 256>>>(attn);
    attn_dot<<<dim3(Bb*HEADS, NSPLIT), dim3(32,32)>>>(A, Bp, attn);
    softmax_M<<<Bb*HEADS, 1024>>>(att_p_w, temp, attn, invQ, invK, M);
    conv1x1_batch<<<PGRD, PBLK>>>(D, M, E);

    // ---- row attention -> out2 (F) ----
    conv1x1_nb<<<PGRD, PBLK>>>(Cp, row_q_w, A);
    conv1x1_nb<<<PGRD, PBLK>>>(Cp, row_k_w, Bp);
    conv1x1_nb<<<PGRD, PBLK>>>(E,  row_v_w, D);
    line_attn<<<Bb*Hh, 512, LA_SMEM>>>(A, Bp, D, Cp, F, row_g, Ww, 1);

    // ---- col attention -> out3 (G) ----
    conv1x1_nb<<<PGRD, PBLK>>>(Cp, col_q_w, A);
    conv1x1_nb<<<PGRD, PBLK>>>(Cp, col_k_w, Bp);
    conv1x1_nb<<<PGRD, PBLK>>>(E,  col_v_w, D);
    line_attn<<<Bb*Ww, 512, LA_SMEM>>>(A, Bp, D, Cp, G, col_g, 1, Ww);

    // ---- fuse + gelu ----
    final_conv<<<PGRD, PBLK, FC_SMEM>>>(E, F, G, conv_w, conv_b, out);
}